// round 10
// baseline (speedup 1.0000x reference)
#include <cuda_runtime.h>
#include <cstdint>

// SpecialSpmmFinal: out[src[e], :] += edge_w[e, :] for e in [0, E)
// N=100000, E=3200000, F=16, fp32. src = edge[0] (first E ints of [2,E]).
//
// R8: lane-transposed scatter (thread -> (edge, 16B piece); a warp's RED.128
// covers 8 nodes x 64 contiguous bytes), now 4 quarter-pieces per thread at
// strides of NQUARTERS/4. 8 independent loads front-batched (deep LSU queue),
// then 4 fire-and-forget red.global.add.v4.f32.

#define N_NODES 100000
#define N_EDGES 3200000
#define FEAT 16
#define NQUARTERS (N_EDGES * 4)       // 12,800,000 quarter-rows
#define QQ (NQUARTERS / 4)            // 3,200,000 per stream

// ---------------------------------------------------------------------------
// Zero the output (harness poisons d_out with 0xAA).
// ---------------------------------------------------------------------------
__global__ void zero_out_kernel(float4* __restrict__ out, int n4) {
    int i = blockIdx.x * blockDim.x + threadIdx.x;
    if (i < n4) out[i] = make_float4(0.f, 0.f, 0.f, 0.f);
}

// ---------------------------------------------------------------------------
// Fire-and-forget 16B float reduction (no "memory" clobber: dest is never
// read in this kernel; nothing may serialize against it).
// ---------------------------------------------------------------------------
__device__ __forceinline__ void red_add_v4(float* dst, float4 v) {
    asm volatile(
        "red.global.add.v4.f32 [%0], {%1, %2, %3, %4};"
        :: "l"(dst), "f"(v.x), "f"(v.y), "f"(v.z), "f"(v.w));
}

// Evict-first 128-bit load (edge_w is touch-once; keep out[] hot in L2).
__device__ __forceinline__ float4 ldcs4(const float4* p) {
    float4 v;
    asm volatile("ld.global.cs.v4.f32 {%0, %1, %2, %3}, [%4];"
                 : "=f"(v.x), "=f"(v.y), "=f"(v.z), "=f"(v.w)
                 : "l"(p));
    return v;
}

// ---------------------------------------------------------------------------
// Lane-transposed scatter-add, 4 pieces per thread.
// Thread t handles quarter-rows t, t+QQ, t+2QQ, t+3QQ:
//   piece q: edge q/4, j = q%4
//   load : w[q]                 (float4; warp = 512 contiguous bytes)
//   index: src[q/4]             (4-lane broadcast)
//   RED  : out[s*16 + j*4]      (warp = 8 nodes x 64 contiguous bytes)
// ---------------------------------------------------------------------------
__global__ void __launch_bounds__(256)
scatter_add_kernel(const int* __restrict__ src,
                   const float4* __restrict__ w,   // [E*4] float4 view of [E,16]
                   float* __restrict__ out) {      // [N,16] f32
    int t = blockIdx.x * blockDim.x + threadIdx.x;
    if (t >= QQ) return;

    const int q0 = t;
    const int q1 = t + QQ;
    const int q2 = t + 2 * QQ;
    const int q3 = t + 3 * QQ;

    // Front-batch all 8 independent loads -> deep LSU queue per thread.
    int    s0 = src[q0 >> 2];
    int    s1 = src[q1 >> 2];
    int    s2 = src[q2 >> 2];
    int    s3 = src[q3 >> 2];
    float4 v0 = ldcs4(w + q0);
    float4 v1 = ldcs4(w + q1);
    float4 v2 = ldcs4(w + q2);
    float4 v3 = ldcs4(w + q3);

    red_add_v4(out + (size_t)s0 * FEAT + (q0 & 3) * 4, v0);
    red_add_v4(out + (size_t)s1 * FEAT + (q1 & 3) * 4, v1);
    red_add_v4(out + (size_t)s2 * FEAT + (q2 & 3) * 4, v2);
    red_add_v4(out + (size_t)s3 * FEAT + (q3 & 3) * 4, v3);
}

// ---------------------------------------------------------------------------
// kernel_launch
// Inputs (metadata order): edge [2,E] int32, edge_w [E,16] f32, then scalars.
// ---------------------------------------------------------------------------
extern "C" void kernel_launch(void* const* d_in, const int* in_sizes, int n_in,
                              void* d_out, int out_size) {
    const int*    src    = (const int*)d_in[0];     // edge[0] = first E ints
    const float4* edge_w = (const float4*)d_in[1];
    float*        out    = (float*)d_out;

    (void)in_sizes; (void)n_in; (void)out_size;

    {
        int n4 = N_NODES * FEAT / 4;                // 400000
        int threads = 512;
        int blocks = (n4 + threads - 1) / threads;  // 782
        zero_out_kernel<<<blocks, threads>>>((float4*)out, n4);
    }

    {
        int threads = 256;
        int blocks = (QQ + threads - 1) / threads;  // 12500
        scatter_add_kernel<<<blocks, threads>>>(src, edge_w, out);
    }
}

// round 12
// speedup vs baseline: 1.0400x; 1.0400x over previous
#include <cuda_runtime.h>
#include <cstdint>

// SpecialSpmmFinal: out[src[e], :] += edge_w[e, :] for e in [0, E)
// N=100000, E=3200000, F=16, fp32. src = edge[0] (first E ints of [2,E]).
//
// R10: R7 scatter (the measured optimum: lane-transposed, 2 quarter-pieces
// per thread — deeper batching regresses via cross-CTA L1tex queue
// contention; scatter sits on the REDG lane-issue floor ~1.29 cyc/lane).
// Zeroing switched from a kernel to cudaMemsetAsync (graph memset node).

#define N_NODES 100000
#define N_EDGES 3200000
#define FEAT 16
#define NQUARTERS (N_EDGES * 4)       // 12,800,000 quarter-rows
#define HALFQ (NQUARTERS / 2)         // 6,400,000

// ---------------------------------------------------------------------------
// Fire-and-forget 16B float reduction (no "memory" clobber: dest is never
// read in this kernel; nothing may serialize against it).
// ---------------------------------------------------------------------------
__device__ __forceinline__ void red_add_v4(float* dst, float4 v) {
    asm volatile(
        "red.global.add.v4.f32 [%0], {%1, %2, %3, %4};"
        :: "l"(dst), "f"(v.x), "f"(v.y), "f"(v.z), "f"(v.w));
}

// Evict-first 128-bit load (edge_w is touch-once; keep out[] hot in L2).
__device__ __forceinline__ float4 ldcs4(const float4* p) {
    float4 v;
    asm volatile("ld.global.cs.v4.f32 {%0, %1, %2, %3}, [%4];"
                 : "=f"(v.x), "=f"(v.y), "=f"(v.z), "=f"(v.w)
                 : "l"(p));
    return v;
}

// ---------------------------------------------------------------------------
// Lane-transposed scatter-add, 2 pieces per thread (R7 optimum).
// Thread t handles quarter-rows t and t+HALFQ:
//   piece q: edge q/4, j = q%4
//   load : w[q]                 (float4; warp = 512 contiguous bytes)
//   index: src[q/4]             (4-lane broadcast)
//   RED  : out[s*16 + j*4]      (warp = 8 nodes x 64 contiguous bytes)
// ---------------------------------------------------------------------------
__global__ void __launch_bounds__(256)
scatter_add_kernel(const int* __restrict__ src,
                   const float4* __restrict__ w,   // [E*4] float4 view of [E,16]
                   float* __restrict__ out) {      // [N,16] f32
    int t = blockIdx.x * blockDim.x + threadIdx.x;
    if (t >= HALFQ) return;

    const int q0 = t;
    const int q1 = t + HALFQ;

    // Front-batch the 4 independent loads (2 idx + 2 data).
    int    s0 = src[q0 >> 2];
    int    s1 = src[q1 >> 2];
    float4 v0 = ldcs4(w + q0);
    float4 v1 = ldcs4(w + q1);

    red_add_v4(out + (size_t)s0 * FEAT + (q0 & 3) * 4, v0);
    red_add_v4(out + (size_t)s1 * FEAT + (q1 & 3) * 4, v1);
}

// ---------------------------------------------------------------------------
// kernel_launch
// Inputs (metadata order): edge [2,E] int32, edge_w [E,16] f32, then scalars.
// ---------------------------------------------------------------------------
extern "C" void kernel_launch(void* const* d_in, const int* in_sizes, int n_in,
                              void* d_out, int out_size) {
    const int*    src    = (const int*)d_in[0];     // edge[0] = first E ints
    const float4* edge_w = (const float4*)d_in[1];
    float*        out    = (float*)d_out;

    (void)in_sizes; (void)n_in; (void)out_size;

    // Zero the output (poisoned to 0xAA by the harness). Async memset is a
    // graph-capturable memset node; IEEE-754 zero == all-zero bytes.
    cudaMemsetAsync(out, 0, (size_t)N_NODES * FEAT * sizeof(float));

    {
        int threads = 256;
        int blocks = (HALFQ + threads - 1) / threads;  // 25000
        scatter_add_kernel<<<blocks, threads>>>(src, edge_w, out);
    }
}